// round 10
// baseline (speedup 1.0000x reference)
#include <cuda_runtime.h>

#define N_  64
#define T_  4096
#define D_  128
#define G_  1024     // total blocks: single wave (<= 148 SMs * 8 CTAs)
#define MAXCH 64     // max chunks per n (true bound ~33)

// Scratch (no allocations allowed anywhere)
__device__ float g_partial[N_ * MAXCH * D_];   // 2 MB
__device__ float g_chunksum[N_ * MAXCH];
__device__ int   g_ticket[N_];                 // zero-init; reset by finisher

// ---------------------------------------------------------------------------
// Cost-balanced fused kernel.
//   live t (t < len): needs key row + value row  -> cost 2
//   dead t (t >= len): w = exp(0) = 1, key row NEVER needed -> cost 1
// Blocks are distributed proportionally to per-n cost S_n = T + len[n]
// (identical deterministic computation on every block), and each n's cost
// range is split into equal-cost chunks via t(s) = s<2len ? s/2 : s-len.
// => all G_ blocks carry equal bytes -> no straggler tail (R9's failure).
// Mainloop bodies are the proven batch-4 / 32-reg / 8-CTA shapes (R4/R8).
// Last block per n (ticket == cnt_n) reduces + normalizes. All sums in fixed
// index order -> deterministic.
// ---------------------------------------------------------------------------
__global__ void __launch_bounds__(256, 8) fused_attn_kernel(
    const float* __restrict__ q,
    const float* __restrict__ key,
    const float* __restrict__ value,
    const int* __restrict__ slen,          // int32 on device (JAX x64 off)
    float* __restrict__ out_ctx,
    float* __restrict__ mask_out)
{
    const int b    = blockIdx.x;
    const int lane = threadIdx.x & 31;
    const int wp   = threadIdx.x >> 5;

    // ---- deterministic cost-proportional assignment: b -> (n, lc, cnt) ----
    int n = 0, kn = 0, cnt = 1, len = 0;
    {
        int C = 0;
#pragma unroll 1
        for (int m2 = 0; m2 < N_; m2++) C += T_ + slen[m2];
        int pref = 0, k_lo = 0;
#pragma unroll 1
        for (int m2 = 0; m2 < N_; m2++) {
            const int S2   = T_ + slen[m2];
            const int k_hi = (int)(((long long)(pref + S2) * G_) / C);
            if (b >= k_lo && b < k_hi) {
                n = m2; kn = k_lo; cnt = k_hi - k_lo; len = S2 - T_;
            }
            pref += S2; k_lo = k_hi;
        }
    }
    const int lc = b - kn;
    const int S  = T_ + len;
    const int s0 = (int)(((long long)lc       * S) / cnt);
    const int s1 = (int)(((long long)(lc + 1) * S) / cnt);
    const int t0 = (s0 < 2 * len) ? (s0 >> 1) : (s0 - len);
    const int t1 = (s1 < 2 * len) ? (s1 >> 1) : (s1 - len);
    const int mb = min(max(len, t0), t1);   // live/dead boundary within [t0,t1]

    // Mask output for this block's t-range (ranges tile [0,T) exactly)
    for (int t = t0 + threadIdx.x; t < t1; t += 256)
        mask_out[(size_t)n * T_ + t] = (t < len) ? 1.0f : 0.0f;

    const float4 qv = reinterpret_cast<const float4*>(q + (size_t)n * D_)[lane];
    const float4* __restrict__ k4 = reinterpret_cast<const float4*>(key);
    const float4* __restrict__ v4 = reinterpret_cast<const float4*>(value);

    const size_t strideT = (size_t)N_ * (D_ / 4);
    const size_t step8   = 8 * strideT;          // warp round-robin stride

    float4 acc = make_float4(0.f, 0.f, 0.f, 0.f);
    float  ws  = 0.0f;

    // ---- live region [t0, mb): key + value, w = exp(dot) ----
    {
        int cw = (mb - t0) - wp;  cw = (cw > 0) ? ((cw + 7) >> 3) : 0;
        size_t o = ((size_t)(t0 + wp) * N_ + n) * (D_ / 4) + lane;
        int j = 0;
        for (; j + 4 <= cw; j += 4) {
            float4 kv[4], vv[4];
#pragma unroll
            for (int u = 0; u < 4; u++) {
                kv[u] = k4[o + (size_t)u * step8];
                vv[u] = v4[o + (size_t)u * step8];
            }
#pragma unroll
            for (int u = 0; u < 4; u++) {
                float p = kv[u].x*qv.x + kv[u].y*qv.y + kv[u].z*qv.z + kv[u].w*qv.w;
                p += __shfl_xor_sync(0xffffffffu, p, 16);
                p += __shfl_xor_sync(0xffffffffu, p, 8);
                p += __shfl_xor_sync(0xffffffffu, p, 4);
                p += __shfl_xor_sync(0xffffffffu, p, 2);
                p += __shfl_xor_sync(0xffffffffu, p, 1);
                const float w = __expf(p);
                ws += w;
                acc.x += w*vv[u].x;  acc.y += w*vv[u].y;
                acc.z += w*vv[u].z;  acc.w += w*vv[u].w;
            }
            o += 4 * step8;
        }
        for (; j < cw; j++) {
            const float4 kv = k4[o];
            const float4 vv = v4[o];
            float p = kv.x*qv.x + kv.y*qv.y + kv.z*qv.z + kv.w*qv.w;
            p += __shfl_xor_sync(0xffffffffu, p, 16);
            p += __shfl_xor_sync(0xffffffffu, p, 8);
            p += __shfl_xor_sync(0xffffffffu, p, 4);
            p += __shfl_xor_sync(0xffffffffu, p, 2);
            p += __shfl_xor_sync(0xffffffffu, p, 1);
            const float w = __expf(p);
            ws += w;
            acc.x += w*vv.x;  acc.y += w*vv.y;  acc.z += w*vv.z;  acc.w += w*vv.w;
            o += step8;
        }
    }

    // ---- dead region [mb, t1): value only, w = exp(0) = 1 ----
    {
        int cw = (t1 - mb) - wp;  cw = (cw > 0) ? ((cw + 7) >> 3) : 0;
        size_t o = ((size_t)(mb + wp) * N_ + n) * (D_ / 4) + lane;
        int j = 0;
        for (; j + 4 <= cw; j += 4) {
            float4 vv[4];
#pragma unroll
            for (int u = 0; u < 4; u++) vv[u] = v4[o + (size_t)u * step8];
            ws += 4.0f;
#pragma unroll
            for (int u = 0; u < 4; u++) {
                acc.x += vv[u].x;  acc.y += vv[u].y;
                acc.z += vv[u].z;  acc.w += vv[u].w;
            }
            o += 4 * step8;
        }
        for (; j < cw; j++) {
            const float4 vv = v4[o];
            ws += 1.0f;
            acc.x += vv.x;  acc.y += vv.y;  acc.z += vv.z;  acc.w += vv.w;
            o += step8;
        }
    }

    // ---- cross-warp reduce (fixed order -> deterministic) ----
    __shared__ float4 red[8][32];
    __shared__ float  wsum[8];
    __shared__ int    isLast;
    red[wp][lane] = acc;
    if (lane == 0) wsum[wp] = ws;
    __syncthreads();

    if (wp == 0) {
        float4 s = red[0][lane];
#pragma unroll
        for (int k = 1; k < 8; k++) {
            const float4 r = red[k][lane];
            s.x += r.x;  s.y += r.y;  s.z += r.z;  s.w += r.w;
        }
        reinterpret_cast<float4*>(g_partial + ((size_t)n * MAXCH + lc) * D_)[lane] = s;
        if (lane == 0) {
            float t = 0.0f;
#pragma unroll
            for (int k = 0; k < 8; k++) t += wsum[k];
            g_chunksum[n * MAXCH + lc] = t;
        }
        __threadfence();
    }
    __syncthreads();

    // ---- completion ticket: last of cnt blocks for this n finishes ----
    if (threadIdx.x == 0)
        isLast = (atomicAdd(&g_ticket[n], 1) == cnt - 1) ? 1 : 0;
    __syncthreads();

    if (isLast) {
        if (threadIdx.x < D_) {
            const int d = threadIdx.x;
            float rs = 0.0f;
            for (int k = 0; k < cnt; k++)
                rs += __ldcg(&g_chunksum[n * MAXCH + k]);
            float s = 0.0f;
            for (int k = 0; k < cnt; k++)
                s += __ldcg(&g_partial[((size_t)n * MAXCH + k) * D_ + d]);
            out_ctx[(size_t)n * D_ + d] = s / rs;
        }
        if (threadIdx.x == 0) g_ticket[n] = 0;   // reset for next replay
    }
}

// ---------------------------------------------------------------------------
extern "C" void kernel_launch(void* const* d_in, const int* in_sizes, int n_in,
                              void* d_out, int out_size)
{
    const float* query = (const float*)d_in[0];
    const float* key   = (const float*)d_in[1];
    const float* value = (const float*)d_in[2];
    const int*   slen  = (const int*)d_in[3];   // int32 on device (JAX x64 off)

    float* out_ctx  = (float*)d_out;           // (N, D)
    float* out_mask = (float*)d_out + N_ * D_; // (N, T)

    fused_attn_kernel<<<G_, 256>>>(query, key, value, slen, out_ctx, out_mask);
}

// round 11
// speedup vs baseline: 1.1642x; 1.1642x over previous
#include <cuda_runtime.h>

#define N_  64
#define T_  4096
#define D_  128
#define G_  1024     // main-kernel blocks: single wave (<= 148 SMs * 8 CTAs)
#define MAXCH 64     // max chunks per n (true bound ~33)

// Scratch (no allocations allowed anywhere)
__device__ float g_partial[N_ * MAXCH * D_];   // 2 MB
__device__ float g_chunksum[N_ * MAXCH];
__device__ int   g_ticket[N_];                 // zero-init; reset by finisher
__device__ int4  g_btab[G_];                   // per-block (n, lc, cnt, len)

// ---------------------------------------------------------------------------
// Setup kernel: computes the cost-proportional block assignment ONCE.
//   cost of n: S_n = T + len[n]  (live t costs 2 rows, dead t costs 1)
//   block range of n: [round(pref_n*G/C), round(pref_{n+1}*G/C))
// 1 block, 64 threads; serial prefix on thread 0 (64 adds). <2us.
// ---------------------------------------------------------------------------
__global__ void setup_kernel(const int* __restrict__ slen)
{
    __shared__ int sS[N_];
    __shared__ int sKlo[N_ + 1];
    const int tid = threadIdx.x;
    if (tid < N_) sS[tid] = T_ + slen[tid];
    __syncthreads();
    if (tid == 0) {
        int C = 0;
        for (int m = 0; m < N_; m++) C += sS[m];
        int pref = 0;
        sKlo[0] = 0;
        for (int m = 0; m < N_; m++) {
            pref += sS[m];
            sKlo[m + 1] = (int)(((long long)pref * G_) / C);
        }
    }
    __syncthreads();
    if (tid < N_) {
        const int k_lo = sKlo[tid], k_hi = sKlo[tid + 1];
        const int len  = sS[tid] - T_;
        const int cnt  = k_hi - k_lo;      // >= 8 (S_n >= T), <= ~33
        for (int b = k_lo; b < k_hi; b++)
            g_btab[b] = make_int4(tid, b - k_lo, cnt, len);
    }
}

// ---------------------------------------------------------------------------
// Cost-balanced fused kernel (R10 mainloop; prologue = 1 table load).
//   live t (t < len): key + value, w = exp(dot)
//   dead t (t >= len): value only, w = exp(0) = 1 (key never needed!)
// Each n's cost range [0, S_n) is split into equal-cost chunks via
// t(s) = s<2len ? s/2 : s-len  -> all blocks carry ~equal bytes.
// Last block per n (ticket == cnt) reduces + normalizes. All sums in fixed
// index order -> deterministic.
// ---------------------------------------------------------------------------
__global__ void __launch_bounds__(256, 8) fused_attn_kernel(
    const float* __restrict__ q,
    const float* __restrict__ key,
    const float* __restrict__ value,
    float* __restrict__ out_ctx,
    float* __restrict__ mask_out)
{
    const int lane = threadIdx.x & 31;
    const int wp   = threadIdx.x >> 5;

    const int4 tab = g_btab[blockIdx.x];      // broadcast load
    const int  n = tab.x, lc = tab.y, cnt = tab.z, len = tab.w;

    const int S  = T_ + len;
    const int s0 = (int)(((long long)lc       * S) / cnt);
    const int s1 = (int)(((long long)(lc + 1) * S) / cnt);
    const int t0 = (s0 < 2 * len) ? (s0 >> 1) : (s0 - len);
    const int t1 = (s1 < 2 * len) ? (s1 >> 1) : (s1 - len);
    const int mb = min(max(len, t0), t1);     // live/dead boundary in [t0,t1]

    // Mask output for this block's t-range (ranges tile [0,T) exactly)
    for (int t = t0 + threadIdx.x; t < t1; t += 256)
        mask_out[(size_t)n * T_ + t] = (t < len) ? 1.0f : 0.0f;

    const float4 qv = reinterpret_cast<const float4*>(q + (size_t)n * D_)[lane];
    const float4* __restrict__ k4 = reinterpret_cast<const float4*>(key);
    const float4* __restrict__ v4 = reinterpret_cast<const float4*>(value);

    const size_t strideT = (size_t)N_ * (D_ / 4);
    const size_t step8   = 8 * strideT;       // warp round-robin stride

    float4 acc = make_float4(0.f, 0.f, 0.f, 0.f);
    float  ws  = 0.0f;

    // ---- live region [t0, mb): key + value, w = exp(dot) ----
    {
        int cw = (mb - t0) - wp;  cw = (cw > 0) ? ((cw + 7) >> 3) : 0;
        size_t o = ((size_t)(t0 + wp) * N_ + n) * (D_ / 4) + lane;
        int j = 0;
        for (; j + 4 <= cw; j += 4) {
            float4 kv[4], vv[4];
#pragma unroll
            for (int u = 0; u < 4; u++) {
                kv[u] = k4[o + (size_t)u * step8];
                vv[u] = v4[o + (size_t)u * step8];
            }
#pragma unroll
            for (int u = 0; u < 4; u++) {
                float p = kv[u].x*qv.x + kv[u].y*qv.y + kv[u].z*qv.z + kv[u].w*qv.w;
                p += __shfl_xor_sync(0xffffffffu, p, 16);
                p += __shfl_xor_sync(0xffffffffu, p, 8);
                p += __shfl_xor_sync(0xffffffffu, p, 4);
                p += __shfl_xor_sync(0xffffffffu, p, 2);
                p += __shfl_xor_sync(0xffffffffu, p, 1);
                const float w = __expf(p);
                ws += w;
                acc.x += w*vv[u].x;  acc.y += w*vv[u].y;
                acc.z += w*vv[u].z;  acc.w += w*vv[u].w;
            }
            o += 4 * step8;
        }
        for (; j < cw; j++) {
            const float4 kv = k4[o];
            const float4 vv = v4[o];
            float p = kv.x*qv.x + kv.y*qv.y + kv.z*qv.z + kv.w*qv.w;
            p += __shfl_xor_sync(0xffffffffu, p, 16);
            p += __shfl_xor_sync(0xffffffffu, p, 8);
            p += __shfl_xor_sync(0xffffffffu, p, 4);
            p += __shfl_xor_sync(0xffffffffu, p, 2);
            p += __shfl_xor_sync(0xffffffffu, p, 1);
            const float w = __expf(p);
            ws += w;
            acc.x += w*vv.x;  acc.y += w*vv.y;  acc.z += w*vv.z;  acc.w += w*vv.w;
            o += step8;
        }
    }

    // ---- dead region [mb, t1): value only, w = exp(0) = 1 ----
    {
        int cw = (t1 - mb) - wp;  cw = (cw > 0) ? ((cw + 7) >> 3) : 0;
        size_t o = ((size_t)(mb + wp) * N_ + n) * (D_ / 4) + lane;
        int j = 0;
        for (; j + 4 <= cw; j += 4) {
            float4 vv[4];
#pragma unroll
            for (int u = 0; u < 4; u++) vv[u] = v4[o + (size_t)u * step8];
            ws += 4.0f;
#pragma unroll
            for (int u = 0; u < 4; u++) {
                acc.x += vv[u].x;  acc.y += vv[u].y;
                acc.z += vv[u].z;  acc.w += vv[u].w;
            }
            o += 4 * step8;
        }
        for (; j < cw; j++) {
            const float4 vv = v4[o];
            ws += 1.0f;
            acc.x += vv.x;  acc.y += vv.y;  acc.z += vv.z;  acc.w += vv.w;
            o += step8;
        }
    }

    // ---- cross-warp reduce (fixed order -> deterministic) ----
    __shared__ float4 red[8][32];
    __shared__ float  wsum[8];
    __shared__ int    isLast;
    red[wp][lane] = acc;
    if (lane == 0) wsum[wp] = ws;
    __syncthreads();

    if (wp == 0) {
        float4 s = red[0][lane];
#pragma unroll
        for (int k = 1; k < 8; k++) {
            const float4 r = red[k][lane];
            s.x += r.x;  s.y += r.y;  s.z += r.z;  s.w += r.w;
        }
        reinterpret_cast<float4*>(g_partial + ((size_t)n * MAXCH + lc) * D_)[lane] = s;
        if (lane == 0) {
            float t = 0.0f;
#pragma unroll
            for (int k = 0; k < 8; k++) t += wsum[k];
            g_chunksum[n * MAXCH + lc] = t;
        }
        __threadfence();
    }
    __syncthreads();

    // ---- completion ticket: last of cnt blocks for this n finishes ----
    if (threadIdx.x == 0)
        isLast = (atomicAdd(&g_ticket[n], 1) == cnt - 1) ? 1 : 0;
    __syncthreads();

    if (isLast) {
        if (threadIdx.x < D_) {
            const int d = threadIdx.x;
            float rs = 0.0f;
            for (int k = 0; k < cnt; k++)
                rs += __ldcg(&g_chunksum[n * MAXCH + k]);
            float s = 0.0f;
            for (int k = 0; k < cnt; k++)
                s += __ldcg(&g_partial[((size_t)n * MAXCH + k) * D_ + d]);
            out_ctx[(size_t)n * D_ + d] = s / rs;
        }
        if (threadIdx.x == 0) g_ticket[n] = 0;   // reset for next replay
    }
}

// ---------------------------------------------------------------------------
extern "C" void kernel_launch(void* const* d_in, const int* in_sizes, int n_in,
                              void* d_out, int out_size)
{
    const float* query = (const float*)d_in[0];
    const float* key   = (const float*)d_in[1];
    const float* value = (const float*)d_in[2];
    const int*   slen  = (const int*)d_in[3];   // int32 on device (JAX x64 off)

    float* out_ctx  = (float*)d_out;           // (N, D)
    float* out_mask = (float*)d_out + N_ * D_; // (N, T)

    setup_kernel<<<1, 64>>>(slen);
    fused_attn_kernel<<<G_, 256>>>(query, key, value, out_ctx, out_mask);
}